// round 17
// baseline (speedup 1.0000x reference)
#include <cuda_runtime.h>
#include <cuda_bf16.h>
#include <cstdint>

// Problem sizes (fixed by the dataset; bounds for static scratch)
static constexpr int NN = 50000;
static constexpr int EE = 800000;

// Scratch (device globals: allocation-free per harness rules)
__device__ __align__(16) float g_x[(long long)NN * 128];  // mlp output [N,128]
__device__ float4 g_h1[NN];        // per-node logits, conv1 (4 heads)
__device__ float4 g_h2[NN];        // per-node logits, conv2 (4 heads)
__device__ int    g_cnt[NN];       // per-src degree
__device__ int    g_off[NN + 1];   // CSR row offsets
__device__ int    g_cur[NN];       // scatter cursors
__device__ int    g_sdst[EE];      // dst sorted by src
__device__ int    g_bsum[64];      // per-block sums for the parallel scan

// ===========================================================================
// Kernel 1: X = feat @ W_mlp + b_mlp via warp-level mma.sync (HMMA, bf16-split)
//   D = Ah*Bh + Ah*Bl + Al*Bh  (hi/lo bf16 decomposition ~ fp32 accuracy)
// BM=128, BN=128, BK=64 staged; 8 warps (2M x 4N), warp tile 64x32.
// ===========================================================================
__device__ __forceinline__ unsigned smem_u32(const void* p) {
    unsigned a;
    asm("{ .reg .u64 t; cvta.to.shared.u64 t, %1; cvt.u32.u64 %0, t; }"
        : "=r"(a) : "l"(p));
    return a;
}

__device__ __forceinline__ void ldsm4(unsigned* r, unsigned addr) {
    asm volatile("ldmatrix.sync.aligned.m8n8.x4.shared.b16 {%0,%1,%2,%3}, [%4];"
                 : "=r"(r[0]), "=r"(r[1]), "=r"(r[2]), "=r"(r[3]) : "r"(addr));
}
__device__ __forceinline__ void ldsm2(unsigned* r, unsigned addr) {
    asm volatile("ldmatrix.sync.aligned.m8n8.x2.shared.b16 {%0,%1}, [%2];"
                 : "=r"(r[0]), "=r"(r[1]) : "r"(addr));
}
__device__ __forceinline__ void mma_bf16(float* d, const unsigned* a, const unsigned* b) {
    asm volatile(
        "mma.sync.aligned.m16n8k16.row.col.f32.bf16.bf16.f32 "
        "{%0,%1,%2,%3}, {%4,%5,%6,%7}, {%8,%9}, {%0,%1,%2,%3};"
        : "+f"(d[0]), "+f"(d[1]), "+f"(d[2]), "+f"(d[3])
        : "r"(a[0]), "r"(a[1]), "r"(a[2]), "r"(a[3]), "r"(b[0]), "r"(b[1]));
}

static constexpr int PITCH  = 144;             // bytes per bf16 smem row (64+8 elems)
static constexpr int SM_AH  = 0;
static constexpr int SM_AL  = 128 * PITCH;     // 18432
static constexpr int SM_BH  = 2 * 128 * PITCH; // 36864
static constexpr int SM_BL  = 3 * 128 * PITCH; // 55296
static constexpr int SM_GEMM = 4 * 128 * PITCH; // 73728 bytes dynamic smem

__global__ __launch_bounds__(256) void gemm_mma_kernel(
    const float* __restrict__ A,     // feat [N,256]
    const float* __restrict__ B,     // W_mlp [256,128]
    const float* __restrict__ bias,  // [128]
    int N)
{
    extern __shared__ __align__(16) char smem[];
    const unsigned sb = smem_u32(smem);
    const int tid  = threadIdx.x;
    const int lane = tid & 31;
    const int wid  = tid >> 5;
    const int wm   = wid >> 2;       // 0..1 (M)
    const int wn   = wid & 3;        // 0..3 (N)
    const int brow = blockIdx.x * 128;

    float acc[4][4][4];
#pragma unroll
    for (int mf = 0; mf < 4; mf++)
#pragma unroll
        for (int nf = 0; nf < 4; nf++)
#pragma unroll
            for (int q = 0; q < 4; q++) acc[mf][nf][q] = 0.f;

    const int a_row = lane & 15;
    const int a_k8  = (lane & 16) ? 8 : 0;
    const int b_row = lane & 7;
    const int b_k8  = (lane & 8) ? 8 : 0;

    for (int ko = 0; ko < 256; ko += 64) {
        // ---- stage A: 128 rows x 64 k, fp32 -> (hi, lo) bf16, padded rows
#pragma unroll
        for (int it = 0; it < 16; it++) {
            int f   = tid + it * 256;
            int row = f >> 5;
            int kc  = (f & 31) * 2;
            int gr  = brow + row;
            float2 v = make_float2(0.f, 0.f);
            if (gr < N) v = *(const float2*)(A + (long long)gr * 256 + ko + kc);
            __nv_bfloat16 h0 = __float2bfloat16(v.x);
            __nv_bfloat16 h1 = __float2bfloat16(v.y);
            __nv_bfloat16 l0 = __float2bfloat16(v.x - __bfloat162float(h0));
            __nv_bfloat16 l1 = __float2bfloat16(v.y - __bfloat162float(h1));
            unsigned wh = (unsigned)__bfloat16_as_ushort(h0)
                        | ((unsigned)__bfloat16_as_ushort(h1) << 16);
            unsigned wl = (unsigned)__bfloat16_as_ushort(l0)
                        | ((unsigned)__bfloat16_as_ushort(l1) << 16);
            *(unsigned*)(smem + SM_AH + row * PITCH + kc * 2) = wh;
            *(unsigned*)(smem + SM_AL + row * PITCH + kc * 2) = wl;
        }
        // ---- stage B: Bt[n][k] bf16 hi/lo; thread packs 2 consecutive k
#pragma unroll
        for (int it = 0; it < 16; it++) {
            int g  = tid + it * 256;
            int n  = g & 127;
            int kw = g >> 7;
            float b0 = __ldg(B + (long long)(ko + 2 * kw + 0) * 128 + n);
            float b1 = __ldg(B + (long long)(ko + 2 * kw + 1) * 128 + n);
            __nv_bfloat16 h0 = __float2bfloat16(b0);
            __nv_bfloat16 h1 = __float2bfloat16(b1);
            __nv_bfloat16 l0 = __float2bfloat16(b0 - __bfloat162float(h0));
            __nv_bfloat16 l1 = __float2bfloat16(b1 - __bfloat162float(h1));
            unsigned wh = (unsigned)__bfloat16_as_ushort(h0)
                        | ((unsigned)__bfloat16_as_ushort(h1) << 16);
            unsigned wl = (unsigned)__bfloat16_as_ushort(l0)
                        | ((unsigned)__bfloat16_as_ushort(l1) << 16);
            *(unsigned*)(smem + SM_BH + n * PITCH + kw * 4) = wh;
            *(unsigned*)(smem + SM_BL + n * PITCH + kw * 4) = wl;
        }
        __syncthreads();

        // ---- MMA over 4 k16 sub-chunks
#pragma unroll
        for (int ks = 0; ks < 64; ks += 16) {
            unsigned ah[4][4], al[4][4], bh[4][2], bl[4][2];
#pragma unroll
            for (int mf = 0; mf < 4; mf++) {
                int r = wm * 64 + mf * 16 + a_row;
                unsigned off = (unsigned)(r * PITCH + (ks + a_k8) * 2);
                ldsm4(ah[mf], sb + SM_AH + off);
                ldsm4(al[mf], sb + SM_AL + off);
            }
#pragma unroll
            for (int nf = 0; nf < 4; nf++) {
                int r = wn * 32 + nf * 8 + b_row;
                unsigned off = (unsigned)(r * PITCH + (ks + b_k8) * 2);
                ldsm2(bh[nf], sb + SM_BH + off);
                ldsm2(bl[nf], sb + SM_BL + off);
            }
#pragma unroll
            for (int mf = 0; mf < 4; mf++)
#pragma unroll
                for (int nf = 0; nf < 4; nf++) {
                    mma_bf16(acc[mf][nf], ah[mf], bh[nf]);
                    mma_bf16(acc[mf][nf], ah[mf], bl[nf]);
                    mma_bf16(acc[mf][nf], al[mf], bh[nf]);
                }
        }
        __syncthreads();
    }

    // ---- epilogue
    const int g = lane >> 2;
    const int t = lane & 3;
#pragma unroll
    for (int mf = 0; mf < 4; mf++) {
#pragma unroll
        for (int nf = 0; nf < 4; nf++) {
            int row0 = brow + wm * 64 + mf * 16 + g;
            int row1 = row0 + 8;
            int col  = wn * 32 + nf * 8 + t * 2;
            if (row0 < N) {
                float2 v = make_float2(acc[mf][nf][0] + __ldg(bias + col),
                                       acc[mf][nf][1] + __ldg(bias + col + 1));
                *(float2*)(g_x + (long long)row0 * 128 + col) = v;
            }
            if (row1 < N) {
                float2 v = make_float2(acc[mf][nf][2] + __ldg(bias + col),
                                       acc[mf][nf][3] + __ldg(bias + col + 1));
                *(float2*)(g_x + (long long)row1 * 128 + col) = v;
            }
        }
    }
}

// ---------------------------------------------------------------------------
// Kernel 2: h1 = feat @ W1^T + b1, h2 = feat @ W2^T + b2   (one warp / node)
// ---------------------------------------------------------------------------
__global__ __launch_bounds__(256) void h_kernel(
    const float* __restrict__ feat,
    const float* __restrict__ W1, const float* __restrict__ b1,
    const float* __restrict__ W2, const float* __restrict__ b2,
    int N)
{
    int warp = (blockIdx.x * blockDim.x + threadIdx.x) >> 5;
    if (warp >= N) return;
    int lane = threadIdx.x & 31;

    float a[4] = {0.f, 0.f, 0.f, 0.f};
    float b[4] = {0.f, 0.f, 0.f, 0.f};
    const float* frow = feat + (long long)warp * 256;
#pragma unroll
    for (int kk = 0; kk < 8; kk++) {
        int k   = lane + kk * 32;
        float f = frow[k];
#pragma unroll
        for (int j = 0; j < 4; j++) {
            a[j] = fmaf(f, __ldg(W1 + j * 256 + k), a[j]);
            b[j] = fmaf(f, __ldg(W2 + j * 256 + k), b[j]);
        }
    }
#pragma unroll
    for (int off = 16; off; off >>= 1) {
#pragma unroll
        for (int j = 0; j < 4; j++) {
            a[j] += __shfl_xor_sync(0xFFFFFFFFu, a[j], off);
            b[j] += __shfl_xor_sync(0xFFFFFFFFu, b[j], off);
        }
    }
    if (lane == 0) {
        g_h1[warp] = make_float4(a[0] + b1[0], a[1] + b1[1], a[2] + b1[2], a[3] + b1[3]);
        g_h2[warp] = make_float4(b[0] + b2[0], b[1] + b2[1], b[2] + b2[2], b[3] + b2[3]);
    }
}

// ---------------------------------------------------------------------------
// CSR build: zero, count, PARALLEL 3-pass scan, scatter
// ---------------------------------------------------------------------------
__global__ void zero_cnt_kernel(int N)
{
    int i = blockIdx.x * blockDim.x + threadIdx.x;
    if (i < N) g_cnt[i] = 0;
}

__global__ void count_kernel(const int* __restrict__ ei, int E)
{
    int e = blockIdx.x * blockDim.x + threadIdx.x;
    if (e < E) atomicAdd(&g_cnt[ei[e]], 1);
}

__global__ __launch_bounds__(256) void scan1_kernel(int N)
{
    __shared__ int wsum[8];
    const int b = blockIdx.x;
    const int tid = threadIdx.x, lane = tid & 31, wid = tid >> 5;
    const int base = b * 1024 + tid * 4;

    int v0 = (base + 0 < N) ? g_cnt[base + 0] : 0;
    int v1 = (base + 1 < N) ? g_cnt[base + 1] : 0;
    int v2 = (base + 2 < N) ? g_cnt[base + 2] : 0;
    int v3 = (base + 3 < N) ? g_cnt[base + 3] : 0;
    int t = v0 + v1 + v2 + v3;

    int x = t;
#pragma unroll
    for (int o = 1; o < 32; o <<= 1) {
        int y = __shfl_up_sync(0xFFFFFFFFu, x, o);
        if (lane >= o) x += y;
    }
    if (lane == 31) wsum[wid] = x;
    __syncthreads();
    if (wid == 0 && lane < 8) {
        int s = wsum[lane];
#pragma unroll
        for (int o = 1; o < 8; o <<= 1) {
            int y = __shfl_up_sync(0xFFu, s, o);
            if (lane >= o) s += y;
        }
        wsum[lane] = s;
    }
    __syncthreads();

    int excl = ((wid > 0) ? wsum[wid - 1] : 0) + x - t;
    if (base + 0 < N) g_off[base + 0] = excl;
    if (base + 1 < N) g_off[base + 1] = excl + v0;
    if (base + 2 < N) g_off[base + 2] = excl + v0 + v1;
    if (base + 3 < N) g_off[base + 3] = excl + v0 + v1 + v2;
    if (tid == 0) g_bsum[b] = wsum[7];
}

__global__ void scan2_kernel(int NB)
{
    __shared__ int ws[2];
    const int tid = threadIdx.x, lane = tid & 31, wid = tid >> 5;
    int v = (tid < NB) ? g_bsum[tid] : 0;
    int x = v;
#pragma unroll
    for (int o = 1; o < 32; o <<= 1) {
        int y = __shfl_up_sync(0xFFFFFFFFu, x, o);
        if (lane >= o) x += y;
    }
    if (lane == 31) ws[wid] = x;
    __syncthreads();
    int incl = x + ((wid == 1) ? ws[0] : 0);
    if (tid < NB) g_bsum[tid] = incl - v;
}

__global__ void scan3_kernel(int N, int E)
{
    int i = blockIdx.x * blockDim.x + threadIdx.x;
    if (i < N) {
        int o = g_off[i] + g_bsum[i >> 10];
        g_off[i] = o;
        g_cur[i] = o;
    }
    if (i == 0) g_off[N] = E;
}

__global__ void scatter_kernel(const int* __restrict__ ei, int E)
{
    int e = blockIdx.x * blockDim.x + threadIdx.x;
    if (e < E) {
        int s = ei[e];
        int d = ei[E + e];
        int pos = atomicAdd(&g_cur[s], 1);
        g_sdst[pos] = d;
    }
}

// ---------------------------------------------------------------------------
// Kernel 4: aggregate.  One warp per node, no atomics, FOUR-edge batched ILP:
// 4 independent dst/h2 loads issue together, then 4 x-gathers into 4
// independent accumulators — doubles per-warp MLP vs the 2-edge loop.
// ---------------------------------------------------------------------------
__global__ __launch_bounds__(256) void agg_kernel(
    const float* __restrict__ eps,
    float* __restrict__ OUT,
    int N)
{
    int node = (blockIdx.x * blockDim.x + threadIdx.x) >> 5;
    if (node >= N) return;
    int lane = threadIdx.x & 31;
    int head = lane >> 3;           // 4 heads, 8 lanes each
    int j    = lane * 4;            // feature offset (float4)

    float4 ha = g_h1[node];
    float ha_h = (head < 2) ? (head == 0 ? ha.x : ha.y)
                            : (head == 2 ? ha.z : ha.w);

    int i   = g_off[node];
    int end = g_off[node + 1];

    float4 acc[4];
#pragma unroll
    for (int k = 0; k < 4; k++) acc[k] = make_float4(0.f, 0.f, 0.f, 0.f);

    // 4-edge batches
    for (; i + 4 <= end; i += 4) {
        int d[4];
#pragma unroll
        for (int k = 0; k < 4; k++) d[k] = __ldg(&g_sdst[i + k]);
        float v[4];
#pragma unroll
        for (int k = 0; k < 4; k++) {
            float4 hb = g_h2[d[k]];
            v[k] = ha_h + ((head < 2) ? (head == 0 ? hb.x : hb.y)
                                      : (head == 2 ? hb.z : hb.w));
        }
#pragma unroll
        for (int k = 0; k < 4; k++) {
            if (v[k] > 0.f) {   // relu zero-skip
                float4 xv = *(const float4*)(g_x + (long long)d[k] * 128 + j);
                acc[k].x = fmaf(v[k], xv.x, acc[k].x);
                acc[k].y = fmaf(v[k], xv.y, acc[k].y);
                acc[k].z = fmaf(v[k], xv.z, acc[k].z);
                acc[k].w = fmaf(v[k], xv.w, acc[k].w);
            }
        }
    }
    // tail (0..3 edges)
    for (; i < end; i++) {
        int dd = __ldg(&g_sdst[i]);
        float4 hb = g_h2[dd];
        float v = ha_h + ((head < 2) ? (head == 0 ? hb.x : hb.y)
                                     : (head == 2 ? hb.z : hb.w));
        if (v > 0.f) {
            float4 xv = *(const float4*)(g_x + (long long)dd * 128 + j);
            acc[0].x = fmaf(v, xv.x, acc[0].x);
            acc[0].y = fmaf(v, xv.y, acc[0].y);
            acc[0].z = fmaf(v, xv.z, acc[0].z);
            acc[0].w = fmaf(v, xv.w, acc[0].w);
        }
    }

    float e0 = eps[0];
    float4 xs = *(const float4*)(g_x + (long long)node * 128 + j);
    float4 o;
    o.x = fmaf(e0, xs.x, (acc[0].x + acc[1].x) + (acc[2].x + acc[3].x));
    o.y = fmaf(e0, xs.y, (acc[0].y + acc[1].y) + (acc[2].y + acc[3].y));
    o.z = fmaf(e0, xs.z, (acc[0].z + acc[1].z) + (acc[2].z + acc[3].z));
    o.w = fmaf(e0, xs.w, (acc[0].w + acc[1].w) + (acc[2].w + acc[3].w));
    *(float4*)(OUT + (long long)node * 128 + j) = o;
}

// ---------------------------------------------------------------------------
extern "C" void kernel_launch(void* const* d_in, const int* in_sizes, int n_in,
                              void* d_out, int out_size)
{
    const float* feat  = (const float*)d_in[0];
    const int*   ei    = (const int*)d_in[1];
    const float* W_mlp = (const float*)d_in[2];
    const float* b_mlp = (const float*)d_in[3];
    const float* W1    = (const float*)d_in[4];
    const float* b1    = (const float*)d_in[5];
    const float* W2    = (const float*)d_in[6];
    const float* b2    = (const float*)d_in[7];
    const float* eps   = (const float*)d_in[8];

    const int N = in_sizes[0] / 256;
    const int E = in_sizes[1] / 2;
    float* out = (float*)d_out;

    // One-time stream/event/attr setup (host objects, no device mem)
    static cudaStream_t s_side = nullptr;
    static cudaEvent_t  ev_fork = nullptr, ev_join = nullptr;
    if (!s_side) {
        cudaStreamCreateWithFlags(&s_side, cudaStreamNonBlocking);
        cudaEventCreateWithFlags(&ev_fork, cudaEventDisableTiming);
        cudaEventCreateWithFlags(&ev_join, cudaEventDisableTiming);
        cudaFuncSetAttribute(gemm_mma_kernel,
                             cudaFuncAttributeMaxDynamicSharedMemorySize, SM_GEMM);
    }

    const int NB = (N + 1023) / 1024;

    // Fork: h projections + CSR build on side stream.
    cudaEventRecord(ev_fork, 0);
    cudaStreamWaitEvent(s_side, ev_fork, 0);

    h_kernel<<<(N + 7) / 8, 256, 0, s_side>>>(feat, W1, b1, W2, b2, N);
    zero_cnt_kernel<<<(N + 511) / 512, 512, 0, s_side>>>(N);
    count_kernel<<<(E + 255) / 256, 256, 0, s_side>>>(ei, E);
    scan1_kernel<<<NB, 256, 0, s_side>>>(N);
    scan2_kernel<<<1, 64, 0, s_side>>>(NB);
    scan3_kernel<<<(N + 255) / 256, 256, 0, s_side>>>(N, E);
    scatter_kernel<<<(E + 255) / 256, 256, 0, s_side>>>(ei, E);
    cudaEventRecord(ev_join, s_side);

    // Dense chain on capture (NULL) stream: tensor-pipe GEMM (HMMA).
    gemm_mma_kernel<<<(N + 127) / 128, 256, SM_GEMM>>>(feat, W_mlp, b_mlp, N);

    // Join, then atomic-free aggregation + epilogue.
    cudaStreamWaitEvent(0, ev_join, 0);
    agg_kernel<<<(N + 7) / 8, 256>>>(eps, out, N);
}